// round 3
// baseline (speedup 1.0000x reference)
#include <cuda_runtime.h>
#include <cstdint>

// B=2, S=1024, H=1024, NH=16, HD=64, R=32, TOPK=128
#define TOPK 128

// device scratch (no allocation allowed)
__device__ __align__(16) float g_t[3u * 2048u * 1024u];         // tq,tk,tv
__device__ __align__(16) float g_xa[2048u * 256u];              // x @ [A0..A7]
__device__ __align__(16) float g_heads[8u * 32u * 1024u * 64u]; // [br][b*16+h][s][d]

// ---------------- Kernel 1: t_z = x @ W_z + b_z ----------------
// Two-level accumulation: fold every 64 K-steps to keep rounding error at
// pairwise-BLAS levels (the top-k keep mask downstream is sensitive to it).
__global__ void __launch_bounds__(256) k_base_gemm(
    const float* __restrict__ x,
    const float* __restrict__ W0, const float* __restrict__ b0,
    const float* __restrict__ W1, const float* __restrict__ b1,
    const float* __restrict__ W2, const float* __restrict__ b2)
{
    const int z = blockIdx.z;
    const float* W    = (z == 0) ? W0 : ((z == 1) ? W1 : W2);
    const float* bias = (z == 0) ? b0 : ((z == 1) ? b1 : b2);
    float* C = g_t + (size_t)z * 2048u * 1024u;

    const int m0 = blockIdx.y * 128, n0 = blockIdx.x * 128;
    __shared__ __align__(16) float As[16][128];
    __shared__ __align__(16) float Bs[16][128];

    const int t = threadIdx.x, ty = t >> 4, tx = t & 15;
    float acc[8][8], part[8][8];
#pragma unroll
    for (int i = 0; i < 8; i++)
#pragma unroll
        for (int j = 0; j < 8; j++) acc[i][j] = 0.f;

    const int am = t >> 1, ak = (t & 1) * 8;
    const int bk = t >> 4, bn = (t & 15) * 8;

    for (int kO = 0; kO < 1024; kO += 64) {
#pragma unroll
        for (int i = 0; i < 8; i++)
#pragma unroll
            for (int j = 0; j < 8; j++) part[i][j] = 0.f;

        for (int kt = 0; kt < 4; kt++) {
            const int k0 = kO + kt * 16;
            float4 a0 = *(const float4*)(x + (size_t)(m0 + am) * 1024 + k0 + ak);
            float4 a1 = *(const float4*)(x + (size_t)(m0 + am) * 1024 + k0 + ak + 4);
            float4 w0 = *(const float4*)(W + (size_t)(k0 + bk) * 1024 + n0 + bn);
            float4 w1 = *(const float4*)(W + (size_t)(k0 + bk) * 1024 + n0 + bn + 4);
            As[ak + 0][am] = a0.x; As[ak + 1][am] = a0.y; As[ak + 2][am] = a0.z; As[ak + 3][am] = a0.w;
            As[ak + 4][am] = a1.x; As[ak + 5][am] = a1.y; As[ak + 6][am] = a1.z; As[ak + 7][am] = a1.w;
            *(float4*)&Bs[bk][bn] = w0;  *(float4*)&Bs[bk][bn + 4] = w1;
            __syncthreads();
#pragma unroll
            for (int kk = 0; kk < 16; kk++) {
                float a[8], b[8];
                *(float4*)&a[0] = *(const float4*)&As[kk][ty * 8];
                *(float4*)&a[4] = *(const float4*)&As[kk][ty * 8 + 4];
                *(float4*)&b[0] = *(const float4*)&Bs[kk][tx * 8];
                *(float4*)&b[4] = *(const float4*)&Bs[kk][tx * 8 + 4];
#pragma unroll
                for (int i = 0; i < 8; i++)
#pragma unroll
                    for (int j = 0; j < 8; j++) part[i][j] += a[i] * b[j];
            }
            __syncthreads();
        }
#pragma unroll
        for (int i = 0; i < 8; i++)
#pragma unroll
            for (int j = 0; j < 8; j++) acc[i][j] += part[i][j];
    }
#pragma unroll
    for (int i = 0; i < 8; i++) {
        const int row = m0 + ty * 8 + i;
#pragma unroll
        for (int j4 = 0; j4 < 2; j4++) {
            const int col = n0 + tx * 8 + j4 * 4;
            float4 bb = *(const float4*)(bias + col);
            float4 o;
            o.x = acc[i][j4*4+0] + bb.x; o.y = acc[i][j4*4+1] + bb.y;
            o.z = acc[i][j4*4+2] + bb.z; o.w = acc[i][j4*4+3] + bb.w;
            *(float4*)(C + (size_t)row * 1024 + col) = o;
        }
    }
}

// ---------------- Kernel 2: xa[:, br*32:br*32+32] = x @ A_br ----------------
// Same two-level accumulation (feeds the qs/ks ranking chain).
__global__ void __launch_bounds__(256) k_xa_gemm(
    const float* __restrict__ x,
    const float* A0, const float* A1, const float* A2, const float* A3,
    const float* A4, const float* A5, const float* A6, const float* A7)
{
    const int br = blockIdx.y;
    const float* A;
    switch (br) { case 0: A=A0; break; case 1: A=A1; break; case 2: A=A2; break; case 3: A=A3; break;
                  case 4: A=A4; break; case 5: A=A5; break; case 6: A=A6; break; default: A=A7; }
    const int m0 = blockIdx.x * 64;
    __shared__ float xs[32][64];
    __shared__ __align__(16) float as_[32][32];

    const int t = threadIdx.x;
    const int mm = t >> 2, rb = (t & 3) * 8;
    const int lm = t >> 2, lk = (t & 3) * 8;
    const int akk = t >> 3, ar = (t & 7) * 4;

    float acc[8];
#pragma unroll
    for (int j = 0; j < 8; j++) acc[j] = 0.f;

    for (int k0 = 0; k0 < 1024; k0 += 32) {
        float4 x0 = *(const float4*)(x + (size_t)(m0 + lm) * 1024 + k0 + lk);
        float4 x1 = *(const float4*)(x + (size_t)(m0 + lm) * 1024 + k0 + lk + 4);
        float4 a4 = *(const float4*)(A + (size_t)(k0 + akk) * 32 + ar);
        xs[lk+0][lm]=x0.x; xs[lk+1][lm]=x0.y; xs[lk+2][lm]=x0.z; xs[lk+3][lm]=x0.w;
        xs[lk+4][lm]=x1.x; xs[lk+5][lm]=x1.y; xs[lk+6][lm]=x1.z; xs[lk+7][lm]=x1.w;
        *(float4*)&as_[akk][ar] = a4;
        __syncthreads();
        float part[8];
#pragma unroll
        for (int j = 0; j < 8; j++) part[j] = 0.f;
#pragma unroll
        for (int kk = 0; kk < 32; kk++) {
            const float xv = xs[kk][mm];
#pragma unroll
            for (int j = 0; j < 8; j++) part[j] += xv * as_[kk][rb + j];
        }
#pragma unroll
        for (int j = 0; j < 8; j++) acc[j] += part[j];
        __syncthreads();
    }
    *(float4*)(g_xa + (size_t)(m0+mm)*256 + br*32 + rb)   = make_float4(acc[0],acc[1],acc[2],acc[3]);
    *(float4*)(g_xa + (size_t)(m0+mm)*256 + br*32 + rb+4) = make_float4(acc[4],acc[5],acc[6],acc[7]);
}

// ------- Kernel 3: heads[br] = base(br) + xa_br @ B_br, head layout -------
__global__ void __launch_bounds__(256) k_expand(
    const float* B0, const float* B1, const float* B2, const float* B3,
    const float* B4, const float* B5, const float* B6, const float* B7)
{
    const int br = blockIdx.z;
    const float* Bm;
    switch (br) { case 0: Bm=B0; break; case 1: Bm=B1; break; case 2: Bm=B2; break; case 3: Bm=B3; break;
                  case 4: Bm=B4; break; case 5: Bm=B5; break; case 6: Bm=B6; break; default: Bm=B7; }
    // branches: 0 q,1 k,2 v,3 qs,4 ks,5 qa,6 ka,7 va
    const int baseIdx = (br == 2 || br == 7) ? 2 : ((br == 1 || br == 4 || br == 6) ? 1 : 0);
    const float* tb = g_t + (size_t)baseIdx * 2048u * 1024u;

    const int m0 = blockIdx.y * 64, n0 = blockIdx.x * 64;
    __shared__ __align__(16) float xaS[32][68];
    __shared__ __align__(16) float bS[32][68];

    const int t = threadIdx.x;
    {
        const int m = t >> 2, rr = (t & 3) * 8;
        float4 v0 = *(const float4*)(g_xa + (size_t)(m0+m)*256 + br*32 + rr);
        float4 v1 = *(const float4*)(g_xa + (size_t)(m0+m)*256 + br*32 + rr + 4);
        xaS[rr+0][m]=v0.x; xaS[rr+1][m]=v0.y; xaS[rr+2][m]=v0.z; xaS[rr+3][m]=v0.w;
        xaS[rr+4][m]=v1.x; xaS[rr+5][m]=v1.y; xaS[rr+6][m]=v1.z; xaS[rr+7][m]=v1.w;
    }
    {
        const int r = t >> 3, nn = (t & 7) * 8;
        *(float4*)&bS[r][nn]   = *(const float4*)(Bm + (size_t)r*1024 + n0 + nn);
        *(float4*)&bS[r][nn+4] = *(const float4*)(Bm + (size_t)r*1024 + n0 + nn + 4);
    }
    __syncthreads();

    const int ty = t >> 4, tx = t & 15;
    float acc[4][4];
#pragma unroll
    for (int i = 0; i < 4; i++)
#pragma unroll
        for (int j = 0; j < 4; j++) acc[i][j] = 0.f;
#pragma unroll
    for (int r = 0; r < 32; r++) {
        float4 a4 = *(const float4*)&xaS[r][ty*4];
        float4 b4 = *(const float4*)&bS[r][tx*4];
        acc[0][0]+=a4.x*b4.x; acc[0][1]+=a4.x*b4.y; acc[0][2]+=a4.x*b4.z; acc[0][3]+=a4.x*b4.w;
        acc[1][0]+=a4.y*b4.x; acc[1][1]+=a4.y*b4.y; acc[1][2]+=a4.y*b4.z; acc[1][3]+=a4.y*b4.w;
        acc[2][0]+=a4.z*b4.x; acc[2][1]+=a4.z*b4.y; acc[2][2]+=a4.z*b4.z; acc[2][3]+=a4.z*b4.w;
        acc[3][0]+=a4.w*b4.x; acc[3][1]+=a4.w*b4.y; acc[3][2]+=a4.w*b4.z; acc[3][3]+=a4.w*b4.w;
    }

    const int h = blockIdx.x; // 64-col tile == one head
#pragma unroll
    for (int i = 0; i < 4; i++) {
        const int m = m0 + ty*4 + i, b_ = m >> 10, s = m & 1023;
        float4 base = *(const float4*)(tb + (size_t)m*1024 + n0 + tx*4);
        float4 o;
        o.x=acc[i][0]+base.x; o.y=acc[i][1]+base.y; o.z=acc[i][2]+base.z; o.w=acc[i][3]+base.w;
        *(float4*)(g_heads + (((size_t)br*32 + b_*16 + h)*1024 + s)*64 + tx*4) = o;
    }
}

// ---------------- Kernel 4: attention ----------------
__device__ __forceinline__ unsigned fmap(float f) {
    unsigned u = __float_as_uint(f);
    return (u & 0x80000000u) ? ~u : (u | 0x80000000u);
}
__device__ __forceinline__ float hred_max(float v) {
#pragma unroll
    for (int o = 1; o < 16; o <<= 1) v = fmaxf(v, __shfl_xor_sync(0xffffffffu, v, o));
    return v;
}
__device__ __forceinline__ float hred_sum(float v) {
#pragma unroll
    for (int o = 1; o < 16; o <<= 1) v += __shfl_xor_sync(0xffffffffu, v, o);
    return v;
}

template<bool KEEP>
__device__ void attn_phase(
    const int t,
    const float* __restrict__ qptr, const float* __restrict__ kptr,
    const float* __restrict__ vptr, const float* __restrict__ maskS,
    float* qv, float* ktile, float* pbuf,
    const float* __restrict__ sc, const unsigned* __restrict__ kth,
    float* m_sh, float* l_sh, float* fac, float* tred, float* oacc)
{
    {
        const int q = t >> 4, d = (t & 15) * 4;
        *(float4*)&qv[q*68 + d] = *(const float4*)(qptr + (size_t)q*64 + d);
    }
    if (t < 16) { m_sh[t] = -1e30f; l_sh[t] = 0.f; }
    for (int i = t; i < 16*68; i += 256) oacc[i] = 0.f;

    float o[4][4];
#pragma unroll
    for (int i = 0; i < 4; i++)
#pragma unroll
        for (int j = 0; j < 4; j++) o[i][j] = 0.f;

    const int q = t >> 4, kb = t & 15;
    const int dg = t & 15, kg = (t >> 4) & 3, qg = t >> 6;
    __syncthreads();

    for (int kt = 0; kt < 8; kt++) {
        { // load K tile 128x64
            const int kloc = t >> 1, dd = (t & 1) * 32;
            const float* src = kptr + ((size_t)kt*128 + kloc)*64 + dd;
            float* dst = ktile + kloc*68 + dd;
#pragma unroll
            for (int jj = 0; jj < 8; jj++) *(float4*)(dst + jj*4) = *(const float4*)(src + jj*4);
        }
        __syncthreads();

        float s[8]; bool keepF[8];
        {
            float4 a4[8];
#pragma unroll
            for (int j = 0; j < 8; j++) a4[j] = make_float4(0.f,0.f,0.f,0.f);
            const float4* qv4 = (const float4*)(qv + q*68);
#pragma unroll
            for (int d4 = 0; d4 < 16; d4++) {
                const float4 qf = qv4[d4];
#pragma unroll
                for (int j = 0; j < 8; j++) {
                    const float4 kf = *(const float4*)(ktile + (kb + 16*j)*68 + d4*4);
                    a4[j].x += qf.x*kf.x; a4[j].y += qf.y*kf.y;
                    a4[j].z += qf.z*kf.z; a4[j].w += qf.w*kf.w;
                }
            }
            float tmax = -1e30f;
#pragma unroll
            for (int j = 0; j < 8; j++) {
                const int key = kt*128 + kb + 16*j;
                float sv = (a4[j].x + a4[j].y + a4[j].z + a4[j].w) * 0.125f + maskS[key];
                if (KEEP) {
                    keepF[j] = (fmap(sc[q*1024 + key]) >= kth[q]);
                    if (!keepF[j]) sv = -1e30f;
                } else keepF[j] = true;
                s[j] = sv;
                tmax = fmaxf(tmax, sv);
            }
            tmax = hred_max(tmax);
            if (kb == 0) tred[q] = tmax;
        }
        __syncthreads();
        if (t < 16) {
            const float nm = fmaxf(m_sh[t], tred[t]);
            fac[t] = __expf(m_sh[t] - nm);
            m_sh[t] = nm;
        }
        __syncthreads();
        {
            const float mq = m_sh[q];
            float ps = 0.f;
#pragma unroll
            for (int j = 0; j < 8; j++) {
                float p = __expf(s[j] - mq);
                if (KEEP && !keepF[j]) p = 0.f;
                pbuf[q*128 + kb + 16*j] = p;
                ps += p;
            }
            ps = hred_sum(ps);
            if (kb == 0) tred[q] = ps;
        }
        __syncthreads();
        if (t < 16) l_sh[t] = l_sh[t] * fac[t] + tred[t];
#pragma unroll
        for (int qi = 0; qi < 4; qi++) {
            const float f = fac[qg*4 + qi];
            o[qi][0]*=f; o[qi][1]*=f; o[qi][2]*=f; o[qi][3]*=f;
        }
        { // load V tile over ktile
            const int kloc = t >> 1, dd = (t & 1) * 32;
            const float* src = vptr + ((size_t)kt*128 + kloc)*64 + dd;
            float* dst = ktile + kloc*68 + dd;
#pragma unroll
            for (int jj = 0; jj < 8; jj++) *(float4*)(dst + jj*4) = *(const float4*)(src + jj*4);
        }
        __syncthreads();
#pragma unroll 8
        for (int kk = 0; kk < 32; kk++) {
            const int kloc = kg*32 + kk;
            const float4 vv = *(const float4*)(ktile + kloc*68 + dg*4);
            const float p0 = pbuf[(qg*4+0)*128 + kloc];
            const float p1 = pbuf[(qg*4+1)*128 + kloc];
            const float p2 = pbuf[(qg*4+2)*128 + kloc];
            const float p3 = pbuf[(qg*4+3)*128 + kloc];
            o[0][0]+=p0*vv.x; o[0][1]+=p0*vv.y; o[0][2]+=p0*vv.z; o[0][3]+=p0*vv.w;
            o[1][0]+=p1*vv.x; o[1][1]+=p1*vv.y; o[1][2]+=p1*vv.z; o[1][3]+=p1*vv.w;
            o[2][0]+=p2*vv.x; o[2][1]+=p2*vv.y; o[2][2]+=p2*vv.z; o[2][3]+=p2*vv.w;
            o[3][0]+=p3*vv.x; o[3][1]+=p3*vv.y; o[3][2]+=p3*vv.z; o[3][3]+=p3*vv.w;
        }
        __syncthreads();
    }

    for (int turn = 0; turn < 4; turn++) {
        if (kg == turn) {
#pragma unroll
            for (int qi = 0; qi < 4; qi++) {
                float* dst = oacc + (qg*4 + qi)*68 + dg*4;
                dst[0]+=o[qi][0]; dst[1]+=o[qi][1]; dst[2]+=o[qi][2]; dst[3]+=o[qi][3];
            }
        }
        __syncthreads();
    }
    for (int i = t; i < 16*64; i += 256) {
        const int qq = i >> 6, d = i & 63;
        oacc[qq*68 + d] *= 0.5f / l_sh[qq];
    }
    __syncthreads();
}

#define SMEM_BYTES (126016)

__global__ void __launch_bounds__(256) k_attention(
    const float* __restrict__ am, float* __restrict__ out)
{
    extern __shared__ float smf[];
    float* sc    = smf;                 // 16*1024
    float* ktile = sc + 16*1024;        // 128*68
    float* qv    = ktile + 128*68;      // 16*68
    float* maskS = qv + 16*68;          // 1024
    float* pbuf  = maskS + 1024;        // 16*128
    float* oaccB = pbuf + 16*128;       // 16*68
    float* oaccC = oaccB + 16*68;       // 16*68
    float* m_sh  = oaccC + 16*68;       // 16
    float* l_sh  = m_sh + 16;
    float* fac   = l_sh + 16;
    float* tred  = fac + 16;
    unsigned* kth = (unsigned*)(tred + 16);

    const int t = threadIdx.x;
    const int head = blockIdx.y;        // b*16 + h
    const int q0 = blockIdx.x * 16;
    const int b_ = head >> 4;

    for (int i = t; i < 1024; i += 256) maskS[i] = am[b_*1024 + i];

    const size_t hs = (size_t)1024 * 64;
    const float* Tq  = g_heads + (0u*32 + head)*hs;
    const float* Tk  = g_heads + (1u*32 + head)*hs;
    const float* Tv  = g_heads + (2u*32 + head)*hs;
    const float* Tqs = g_heads + (3u*32 + head)*hs;
    const float* Tks = g_heads + (4u*32 + head)*hs;
    const float* Tqa = g_heads + (5u*32 + head)*hs;
    const float* Tka = g_heads + (6u*32 + head)*hs;
    const float* Tva = g_heads + (7u*32 + head)*hs;

    // Phase A: sc_est rows + exact 128th-largest threshold per query
    {
        const int q = t >> 4, d = (t & 15) * 4;
        *(float4*)&qv[q*68 + d] = *(const float4*)(Tqs + (size_t)(q0+q)*64 + d);
    }
    __syncthreads();

    const int q = t >> 4, kb = t & 15;
    for (int kt = 0; kt < 8; kt++) {
        {
            const int kloc = t >> 1, dd = (t & 1) * 32;
            const float* src = Tks + ((size_t)kt*128 + kloc)*64 + dd;
            float* dst = ktile + kloc*68 + dd;
#pragma unroll
            for (int jj = 0; jj < 8; jj++) *(float4*)(dst + jj*4) = *(const float4*)(src + jj*4);
        }
        __syncthreads();
        {
            float4 a4[8];
#pragma unroll
            for (int j = 0; j < 8; j++) a4[j] = make_float4(0.f,0.f,0.f,0.f);
            const float4* qv4 = (const float4*)(qv + q*68);
#pragma unroll
            for (int d4 = 0; d4 < 16; d4++) {
                const float4 qf = qv4[d4];
#pragma unroll
                for (int j = 0; j < 8; j++) {
                    const float4 kf = *(const float4*)(ktile + (kb + 16*j)*68 + d4*4);
                    a4[j].x += qf.x*kf.x; a4[j].y += qf.y*kf.y;
                    a4[j].z += qf.z*kf.z; a4[j].w += qf.w*kf.w;
                }
            }
#pragma unroll
            for (int j = 0; j < 8; j++) {
                const int key = kt*128 + kb + 16*j;
                sc[q*1024 + key] = (a4[j].x + a4[j].y + a4[j].z + a4[j].w) * 0.125f + maskS[key];
            }
        }
        __syncthreads();
    }

    { // exact k-th largest via 32-step binary search over monotone uint map
        const int w = t >> 5, lane = t & 31;
        for (int rep = 0; rep < 2; rep++) {
            const int qq = w*2 + rep;
            unsigned uv[32];
#pragma unroll
            for (int i = 0; i < 32; i++) uv[i] = fmap(sc[qq*1024 + i*32 + lane]);
            unsigned lo = 0u, hi = 0xFFFFFFFFu;
            while (lo < hi) {
                const unsigned dd = hi - lo;
                const unsigned mid = lo + (dd >> 1) + (dd & 1u);
                int c = 0;
#pragma unroll
                for (int i = 0; i < 32; i++) c += (uv[i] >= mid) ? 1 : 0;
#pragma unroll
                for (int off = 1; off < 32; off <<= 1) c += __shfl_xor_sync(0xffffffffu, c, off);
                if (c >= TOPK) lo = mid; else hi = mid - 1;
            }
            if (lane == 0) kth[qq] = lo;
        }
    }
    __syncthreads();

    // Phase B: est branch (dense softmax over qa.ka, accumulate @ va)
    attn_phase<false>(t, Tqa + (size_t)q0*64, Tka, Tva, maskS,
                      qv, ktile, pbuf, sc, kth, m_sh, l_sh, fac, tred, oaccB);
    // Phase C: sparse branch (keep-masked softmax over q.k, accumulate @ v)
    attn_phase<true>(t, Tq + (size_t)q0*64, Tk, Tv, maskS,
                     qv, ktile, pbuf, sc, kth, m_sh, l_sh, fac, tred, oaccC);

    for (int i = t; i < 16*64; i += 256) {
        const int qq = i >> 6, d = i & 63;
        const float val = oaccB[qq*68 + d] + oaccC[qq*68 + d];
        out[((size_t)(b_*1024 + q0 + qq))*1024 + (head & 15)*64 + d] = val;
    }
}

// ---------------- host ----------------
extern "C" void kernel_launch(void* const* d_in, const int* in_sizes, int n_in,
                              void* d_out, int out_size) {
    const float* x  = (const float*)d_in[0];
    const float* am = (const float*)d_in[1];
    const float* Wq = (const float*)d_in[2]; const float* bq = (const float*)d_in[3];
    const float* Wk = (const float*)d_in[4]; const float* bk = (const float*)d_in[5];
    const float* Wv = (const float*)d_in[6]; const float* bv = (const float*)d_in[7];
    const float* A[8]; const float* Bm[8];
    for (int i = 0; i < 8; i++) { A[i] = (const float*)d_in[8 + 2*i]; Bm[i] = (const float*)d_in[9 + 2*i]; }
    float* out = (float*)d_out;

    cudaFuncSetAttribute(k_attention, cudaFuncAttributeMaxDynamicSharedMemorySize, SMEM_BYTES);

    k_base_gemm<<<dim3(8, 16, 3), 256>>>(x, Wq, bq, Wk, bk, Wv, bv);
    k_xa_gemm<<<dim3(32, 8), 256>>>(x, A[0],A[1],A[2],A[3],A[4],A[5],A[6],A[7]);
    k_expand<<<dim3(16, 32, 8), 256>>>(Bm[0],Bm[1],Bm[2],Bm[3],Bm[4],Bm[5],Bm[6],Bm[7]);
    k_attention<<<dim3(64, 32), 256, SMEM_BYTES>>>(am, out);
}

// round 4
// speedup vs baseline: 1.3147x; 1.3147x over previous
#include <cuda_runtime.h>
#include <cstdint>

// B=2, S=1024, H=1024, NH=16, HD=64, R=32, TOPK=128
#define TOPK 128

// device scratch (no allocation allowed)
__device__ __align__(16) float g_t[3u * 2048u * 1024u];         // tq,tk,tv
__device__ __align__(16) float g_xa[2048u * 256u];              // x @ [A0..A7]
__device__ __align__(16) float g_heads[8u * 32u * 1024u * 64u]; // [br][b*16+h][s][d]

// ---------------- Kernel 1: t_z = x @ W_z + b_z ----------------
__global__ void __launch_bounds__(256) k_base_gemm(
    const float* __restrict__ x,
    const float* __restrict__ W0, const float* __restrict__ b0,
    const float* __restrict__ W1, const float* __restrict__ b1,
    const float* __restrict__ W2, const float* __restrict__ b2)
{
    const int z = blockIdx.z;
    const float* W    = (z == 0) ? W0 : ((z == 1) ? W1 : W2);
    const float* bias = (z == 0) ? b0 : ((z == 1) ? b1 : b2);
    float* C = g_t + (size_t)z * 2048u * 1024u;

    const int m0 = blockIdx.y * 128, n0 = blockIdx.x * 128;
    __shared__ __align__(16) float As[16][128];
    __shared__ __align__(16) float Bs[16][128];

    const int t = threadIdx.x, ty = t >> 4, tx = t & 15;
    float acc[8][8], part[8][8];
#pragma unroll
    for (int i = 0; i < 8; i++)
#pragma unroll
        for (int j = 0; j < 8; j++) acc[i][j] = 0.f;

    const int am = t >> 1, ak = (t & 1) * 8;
    const int bk = t >> 4, bn = (t & 15) * 8;

    for (int kO = 0; kO < 1024; kO += 64) {
#pragma unroll
        for (int i = 0; i < 8; i++)
#pragma unroll
            for (int j = 0; j < 8; j++) part[i][j] = 0.f;

        for (int kt = 0; kt < 4; kt++) {
            const int k0 = kO + kt * 16;
            float4 a0 = *(const float4*)(x + (size_t)(m0 + am) * 1024 + k0 + ak);
            float4 a1 = *(const float4*)(x + (size_t)(m0 + am) * 1024 + k0 + ak + 4);
            float4 w0 = *(const float4*)(W + (size_t)(k0 + bk) * 1024 + n0 + bn);
            float4 w1 = *(const float4*)(W + (size_t)(k0 + bk) * 1024 + n0 + bn + 4);
            As[ak + 0][am] = a0.x; As[ak + 1][am] = a0.y; As[ak + 2][am] = a0.z; As[ak + 3][am] = a0.w;
            As[ak + 4][am] = a1.x; As[ak + 5][am] = a1.y; As[ak + 6][am] = a1.z; As[ak + 7][am] = a1.w;
            *(float4*)&Bs[bk][bn] = w0;  *(float4*)&Bs[bk][bn + 4] = w1;
            __syncthreads();
#pragma unroll
            for (int kk = 0; kk < 16; kk++) {
                float a[8], b[8];
                *(float4*)&a[0] = *(const float4*)&As[kk][ty * 8];
                *(float4*)&a[4] = *(const float4*)&As[kk][ty * 8 + 4];
                *(float4*)&b[0] = *(const float4*)&Bs[kk][tx * 8];
                *(float4*)&b[4] = *(const float4*)&Bs[kk][tx * 8 + 4];
#pragma unroll
                for (int i = 0; i < 8; i++)
#pragma unroll
                    for (int j = 0; j < 8; j++) part[i][j] += a[i] * b[j];
            }
            __syncthreads();
        }
#pragma unroll
        for (int i = 0; i < 8; i++)
#pragma unroll
            for (int j = 0; j < 8; j++) acc[i][j] += part[i][j];
    }
#pragma unroll
    for (int i = 0; i < 8; i++) {
        const int row = m0 + ty * 8 + i;
#pragma unroll
        for (int j4 = 0; j4 < 2; j4++) {
            const int col = n0 + tx * 8 + j4 * 4;
            float4 bb = *(const float4*)(bias + col);
            float4 o;
            o.x = acc[i][j4*4+0] + bb.x; o.y = acc[i][j4*4+1] + bb.y;
            o.z = acc[i][j4*4+2] + bb.z; o.w = acc[i][j4*4+3] + bb.w;
            *(float4*)(C + (size_t)row * 1024 + col) = o;
        }
    }
}

// ---------------- Kernel 2: xa[:, br*32:br*32+32] = x @ A_br ----------------
__global__ void __launch_bounds__(256) k_xa_gemm(
    const float* __restrict__ x,
    const float* A0, const float* A1, const float* A2, const float* A3,
    const float* A4, const float* A5, const float* A6, const float* A7)
{
    const int br = blockIdx.y;
    const float* A;
    switch (br) { case 0: A=A0; break; case 1: A=A1; break; case 2: A=A2; break; case 3: A=A3; break;
                  case 4: A=A4; break; case 5: A=A5; break; case 6: A=A6; break; default: A=A7; }
    const int m0 = blockIdx.x * 64;
    __shared__ float xs[32][64];
    __shared__ __align__(16) float as_[32][32];

    const int t = threadIdx.x;
    const int mm = t >> 2, rb = (t & 3) * 8;
    const int lm = t >> 2, lk = (t & 3) * 8;
    const int akk = t >> 3, ar = (t & 7) * 4;

    float acc[8];
#pragma unroll
    for (int j = 0; j < 8; j++) acc[j] = 0.f;

    for (int k0 = 0; k0 < 1024; k0 += 32) {
        float4 x0 = *(const float4*)(x + (size_t)(m0 + lm) * 1024 + k0 + lk);
        float4 x1 = *(const float4*)(x + (size_t)(m0 + lm) * 1024 + k0 + lk + 4);
        float4 a4 = *(const float4*)(A + (size_t)(k0 + akk) * 32 + ar);
        xs[lk+0][lm]=x0.x; xs[lk+1][lm]=x0.y; xs[lk+2][lm]=x0.z; xs[lk+3][lm]=x0.w;
        xs[lk+4][lm]=x1.x; xs[lk+5][lm]=x1.y; xs[lk+6][lm]=x1.z; xs[lk+7][lm]=x1.w;
        *(float4*)&as_[akk][ar] = a4;
        __syncthreads();
        float part[8];
#pragma unroll
        for (int j = 0; j < 8; j++) part[j] = 0.f;
#pragma unroll
        for (int kk = 0; kk < 32; kk++) {
            const float xv = xs[kk][mm];
#pragma unroll
            for (int j = 0; j < 8; j++) part[j] += xv * as_[kk][rb + j];
        }
#pragma unroll
        for (int j = 0; j < 8; j++) acc[j] += part[j];
        __syncthreads();
    }
    *(float4*)(g_xa + (size_t)(m0+mm)*256 + br*32 + rb)   = make_float4(acc[0],acc[1],acc[2],acc[3]);
    *(float4*)(g_xa + (size_t)(m0+mm)*256 + br*32 + rb+4) = make_float4(acc[4],acc[5],acc[6],acc[7]);
}

// ------- Kernel 3: heads[br] = base(br) + xa_br @ B_br, head layout -------
__global__ void __launch_bounds__(256) k_expand(
    const float* B0, const float* B1, const float* B2, const float* B3,
    const float* B4, const float* B5, const float* B6, const float* B7)
{
    const int br = blockIdx.z;
    const float* Bm;
    switch (br) { case 0: Bm=B0; break; case 1: Bm=B1; break; case 2: Bm=B2; break; case 3: Bm=B3; break;
                  case 4: Bm=B4; break; case 5: Bm=B5; break; case 6: Bm=B6; break; default: Bm=B7; }
    const int baseIdx = (br == 2 || br == 7) ? 2 : ((br == 1 || br == 4 || br == 6) ? 1 : 0);
    const float* tb = g_t + (size_t)baseIdx * 2048u * 1024u;

    const int m0 = blockIdx.y * 64, n0 = blockIdx.x * 64;
    __shared__ __align__(16) float xaS[32][68];
    __shared__ __align__(16) float bS[32][68];

    const int t = threadIdx.x;
    {
        const int m = t >> 2, rr = (t & 3) * 8;
        float4 v0 = *(const float4*)(g_xa + (size_t)(m0+m)*256 + br*32 + rr);
        float4 v1 = *(const float4*)(g_xa + (size_t)(m0+m)*256 + br*32 + rr + 4);
        xaS[rr+0][m]=v0.x; xaS[rr+1][m]=v0.y; xaS[rr+2][m]=v0.z; xaS[rr+3][m]=v0.w;
        xaS[rr+4][m]=v1.x; xaS[rr+5][m]=v1.y; xaS[rr+6][m]=v1.z; xaS[rr+7][m]=v1.w;
    }
    {
        const int r = t >> 3, nn = (t & 7) * 8;
        *(float4*)&bS[r][nn]   = *(const float4*)(Bm + (size_t)r*1024 + n0 + nn);
        *(float4*)&bS[r][nn+4] = *(const float4*)(Bm + (size_t)r*1024 + n0 + nn + 4);
    }
    __syncthreads();

    const int ty = t >> 4, tx = t & 15;
    float acc[4][4];
#pragma unroll
    for (int i = 0; i < 4; i++)
#pragma unroll
        for (int j = 0; j < 4; j++) acc[i][j] = 0.f;
#pragma unroll
    for (int r = 0; r < 32; r++) {
        float4 a4 = *(const float4*)&xaS[r][ty*4];
        float4 b4 = *(const float4*)&bS[r][tx*4];
        acc[0][0]+=a4.x*b4.x; acc[0][1]+=a4.x*b4.y; acc[0][2]+=a4.x*b4.z; acc[0][3]+=a4.x*b4.w;
        acc[1][0]+=a4.y*b4.x; acc[1][1]+=a4.y*b4.y; acc[1][2]+=a4.y*b4.z; acc[1][3]+=a4.y*b4.w;
        acc[2][0]+=a4.z*b4.x; acc[2][1]+=a4.z*b4.y; acc[2][2]+=a4.z*b4.z; acc[2][3]+=a4.z*b4.w;
        acc[3][0]+=a4.w*b4.x; acc[3][1]+=a4.w*b4.y; acc[3][2]+=a4.w*b4.z; acc[3][3]+=a4.w*b4.w;
    }

    const int h = blockIdx.x;
#pragma unroll
    for (int i = 0; i < 4; i++) {
        const int m = m0 + ty*4 + i, b_ = m >> 10, s = m & 1023;
        float4 base = *(const float4*)(tb + (size_t)m*1024 + n0 + tx*4);
        float4 o;
        o.x=acc[i][0]+base.x; o.y=acc[i][1]+base.y; o.z=acc[i][2]+base.z; o.w=acc[i][3]+base.w;
        *(float4*)(g_heads + (((size_t)br*32 + b_*16 + h)*1024 + s)*64 + tx*4) = o;
    }
}

// ---------------- Kernel 4: attention (v2) ----------------
__device__ __forceinline__ unsigned fmap(float f) {
    unsigned u = __float_as_uint(f);
    return (u & 0x80000000u) ? ~u : (u | 0x80000000u);
}
__device__ __forceinline__ float wredmax(float v) {
#pragma unroll
    for (int o = 16; o > 0; o >>= 1) v = fmaxf(v, __shfl_xor_sync(0xffffffffu, v, o));
    return v;
}
__device__ __forceinline__ float wredsum(float v) {
#pragma unroll
    for (int o = 16; o > 0; o >>= 1) v += __shfl_xor_sync(0xffffffffu, v, o);
    return v;
}
__device__ __forceinline__ unsigned wredsumu(unsigned v) {
#pragma unroll
    for (int o = 16; o > 0; o >>= 1) v += __shfl_xor_sync(0xffffffffu, v, o);
    return v;
}

// smem float offsets
#define OFF_KTILE 0
#define OFF_VTILE (128*68)
#define OFF_QV    (2*128*68)
#define OFF_MASK  (OFF_QV + 16*68)
#define OFF_PBUF  (OFF_MASK + 1024)
#define OFF_OACCB (OFF_PBUF + 16*128)
#define OFF_OACCC (OFF_OACCB + 16*68)
#define OFF_FAC   (OFF_OACCC + 16*68)
#define OFF_LSH   (OFF_FAC + 16)
#define OFF_KEEP  (OFF_LSH + 16)
#define SMEM_FLOATS (OFF_KEEP + 512)
#define SMEM_BYTES  (SMEM_FLOATS * 4)   // 97,152 B -> 2 CTAs/SM

template<bool KEEP>
__device__ void attn_phase(
    const int t,
    const float* __restrict__ qptr, const float* __restrict__ kptr,
    const float* __restrict__ vptr, const float* __restrict__ maskS,
    float* qv, float* ktile, float* vtile, float* pbuf,
    const unsigned* __restrict__ keepm, float* fac, float* l_sh, float* oacc)
{
    {   // load 16 query rows
        const int q = t >> 4, d = (t & 15) * 4;
        *(float4*)&qv[q*68 + d] = *(const float4*)(qptr + (size_t)q*64 + d);
    }
    for (int i = t; i < 16*68; i += 256) oacc[i] = 0.f;

    float o[4][4];
#pragma unroll
    for (int i = 0; i < 4; i++)
#pragma unroll
        for (int j = 0; j < 4; j++) o[i][j] = 0.f;

    const int qp = t >> 5;                  // warp -> queries 2qp, 2qp+1
    const int kb = t & 31;                  // key slot within tile
    const int dg = t & 15, kg = (t >> 4) & 3, qg = t >> 6;   // pv mapping
    float m0r = -1e30f, m1r = -1e30f, l0r = 0.f, l1r = 0.f;
    __syncthreads();

    for (int kt = 0; kt < 8; kt++) {
        {   // load K and V tiles together (16 outstanding LDGs)
            const int kloc = t >> 1, dd = (t & 1) * 32;
            const float* ksrc = kptr + ((size_t)kt*128 + kloc)*64 + dd;
            const float* vsrc = vptr + ((size_t)kt*128 + kloc)*64 + dd;
            float4 kr[8], vr[8];
#pragma unroll
            for (int jj = 0; jj < 8; jj++) kr[jj] = *(const float4*)(ksrc + jj*4);
#pragma unroll
            for (int jj = 0; jj < 8; jj++) vr[jj] = *(const float4*)(vsrc + jj*4);
            float* kdst = ktile + kloc*68 + dd;
            float* vdst = vtile + kloc*68 + dd;
#pragma unroll
            for (int jj = 0; jj < 8; jj++) *(float4*)(kdst + jj*4) = kr[jj];
#pragma unroll
            for (int jj = 0; jj < 8; jj++) *(float4*)(vdst + jj*4) = vr[jj];
        }
        __syncthreads();                    // S1

        // scores: 2 queries x 4 keys per thread
        float4 a0[4], a1[4];
#pragma unroll
        for (int j = 0; j < 4; j++) { a0[j] = make_float4(0,0,0,0); a1[j] = make_float4(0,0,0,0); }
        const float4* q0v = (const float4*)(qv + (2*qp)*68);
        const float4* q1v = (const float4*)(qv + (2*qp+1)*68);
#pragma unroll
        for (int d4 = 0; d4 < 16; d4++) {
            const float4 f0 = q0v[d4], f1 = q1v[d4];
#pragma unroll
            for (int j = 0; j < 4; j++) {
                const float4 kf = *(const float4*)(ktile + (kb + 32*j)*68 + d4*4);
                a0[j].x += f0.x*kf.x; a0[j].y += f0.y*kf.y; a0[j].z += f0.z*kf.z; a0[j].w += f0.w*kf.w;
                a1[j].x += f1.x*kf.x; a1[j].y += f1.y*kf.y; a1[j].z += f1.z*kf.z; a1[j].w += f1.w*kf.w;
            }
        }
        float s0[4], s1[4]; bool kp0[4], kp1[4];
        float tm0 = -1e30f, tm1 = -1e30f;
#pragma unroll
        for (int j = 0; j < 4; j++) {
            const int key = kt*128 + 32*j + kb;
            const float mv = maskS[key];
            float v0 = (a0[j].x + a0[j].y + a0[j].z + a0[j].w) * 0.125f + mv;
            float v1 = (a1[j].x + a1[j].y + a1[j].z + a1[j].w) * 0.125f + mv;
            if (KEEP) {
                kp0[j] = (keepm[(2*qp)*32   + kt*4 + j] >> kb) & 1u;
                kp1[j] = (keepm[(2*qp+1)*32 + kt*4 + j] >> kb) & 1u;
                if (!kp0[j]) v0 = -1e30f;
                if (!kp1[j]) v1 = -1e30f;
            } else { kp0[j] = true; kp1[j] = true; }
            s0[j] = v0; s1[j] = v1;
            tm0 = fmaxf(tm0, v0); tm1 = fmaxf(tm1, v1);
        }
        tm0 = wredmax(tm0); tm1 = wredmax(tm1);
        const float nm0 = fmaxf(m0r, tm0), nm1 = fmaxf(m1r, tm1);
        const float f0r = __expf(m0r - nm0), f1r = __expf(m1r - nm1);
        m0r = nm0; m1r = nm1;
        if (kb == 0) { fac[2*qp] = f0r; fac[2*qp+1] = f1r; }
        float ps0 = 0.f, ps1 = 0.f;
#pragma unroll
        for (int j = 0; j < 4; j++) {
            float p0 = __expf(s0[j] - nm0);
            float p1 = __expf(s1[j] - nm1);
            if (KEEP && !kp0[j]) p0 = 0.f;
            if (KEEP && !kp1[j]) p1 = 0.f;
            pbuf[(2*qp)*128   + 32*j + kb] = p0;
            pbuf[(2*qp+1)*128 + 32*j + kb] = p1;
            ps0 += p0; ps1 += p1;
        }
        ps0 = wredsum(ps0); ps1 = wredsum(ps1);
        l0r = l0r * f0r + ps0;
        l1r = l1r * f1r + ps1;
        __syncthreads();                    // S2: fac + pbuf visible

        // rescale + accumulate o += p * v
        float fq[4];
#pragma unroll
        for (int qi = 0; qi < 4; qi++) fq[qi] = fac[qg*4 + qi];
#pragma unroll
        for (int qi = 0; qi < 4; qi++) {
            o[qi][0]*=fq[qi]; o[qi][1]*=fq[qi]; o[qi][2]*=fq[qi]; o[qi][3]*=fq[qi];
        }
#pragma unroll 8
        for (int kk = 0; kk < 32; kk++) {
            const int kloc = kg*32 + kk;
            const float4 vv = *(const float4*)(vtile + kloc*68 + dg*4);
            const float p0 = pbuf[(qg*4+0)*128 + kloc];
            const float p1 = pbuf[(qg*4+1)*128 + kloc];
            const float p2 = pbuf[(qg*4+2)*128 + kloc];
            const float p3 = pbuf[(qg*4+3)*128 + kloc];
            o[0][0]+=p0*vv.x; o[0][1]+=p0*vv.y; o[0][2]+=p0*vv.z; o[0][3]+=p0*vv.w;
            o[1][0]+=p1*vv.x; o[1][1]+=p1*vv.y; o[1][2]+=p1*vv.z; o[1][3]+=p1*vv.w;
            o[2][0]+=p2*vv.x; o[2][1]+=p2*vv.y; o[2][2]+=p2*vv.z; o[2][3]+=p2*vv.w;
            o[3][0]+=p3*vv.x; o[3][1]+=p3*vv.y; o[3][2]+=p3*vv.z; o[3][3]+=p3*vv.w;
        }
        __syncthreads();                    // S3: tile done
    }

    if (kb == 0) { l_sh[2*qp] = l0r; l_sh[2*qp+1] = l1r; }
    // merge per-kg partials
    for (int turn = 0; turn < 4; turn++) {
        if (kg == turn) {
#pragma unroll
            for (int qi = 0; qi < 4; qi++) {
                float* dst = oacc + (qg*4 + qi)*68 + dg*4;
                dst[0]+=o[qi][0]; dst[1]+=o[qi][1]; dst[2]+=o[qi][2]; dst[3]+=o[qi][3];
            }
        }
        __syncthreads();
    }
    for (int i = t; i < 16*64; i += 256) {
        const int qq = i >> 6, d = i & 63;
        oacc[qq*68 + d] *= 0.5f / l_sh[qq];
    }
    __syncthreads();
}

__global__ void __launch_bounds__(256, 2) k_attention(
    const float* __restrict__ am, float* __restrict__ out)
{
    extern __shared__ float smf[];
    float* ktile = smf + OFF_KTILE;
    float* vtile = smf + OFF_VTILE;
    float* qv    = smf + OFF_QV;
    float* maskS = smf + OFF_MASK;
    float* pbuf  = smf + OFF_PBUF;
    float* oaccB = smf + OFF_OACCB;
    float* oaccC = smf + OFF_OACCC;
    float* fac   = smf + OFF_FAC;
    float* l_sh  = smf + OFF_LSH;
    unsigned* keepm = (unsigned*)(smf + OFF_KEEP);

    const int t = threadIdx.x;
    const int head = blockIdx.y;        // b*16 + h
    const int q0 = blockIdx.x * 16;
    const int b_ = head >> 4;

    for (int i = t; i < 1024; i += 256) maskS[i] = am[b_*1024 + i];

    const size_t hs = (size_t)1024 * 64;
    const float* Tq  = g_heads + (0u*32 + head)*hs;
    const float* Tk  = g_heads + (1u*32 + head)*hs;
    const float* Tv  = g_heads + (2u*32 + head)*hs;
    const float* Tqs = g_heads + (3u*32 + head)*hs;
    const float* Tks = g_heads + (4u*32 + head)*hs;
    const float* Tqa = g_heads + (5u*32 + head)*hs;
    const float* Tka = g_heads + (6u*32 + head)*hs;
    const float* Tva = g_heads + (7u*32 + head)*hs;

    // ---- Phase A: scores in registers, exact kth threshold, keep bitmask ----
    {
        const int q = t >> 4, d = (t & 15) * 4;
        *(float4*)&qv[q*68 + d] = *(const float4*)(Tqs + (size_t)(q0+q)*64 + d);
    }
    __syncthreads();

    const int qp = t >> 5, kb = t & 31;
    unsigned uv0[32], uv1[32];

    {   // preload tile 0 into ktile
        const int kloc = t >> 1, dd = (t & 1) * 32;
        const float* src = Tks + (size_t)kloc*64 + dd;
        float* dst = ktile + kloc*68 + dd;
#pragma unroll
        for (int jj = 0; jj < 8; jj++) *(float4*)(dst + jj*4) = *(const float4*)(src + jj*4);
    }
    __syncthreads();

#pragma unroll
    for (int kt = 0; kt < 8; kt++) {
        float* cur = (kt & 1) ? vtile : ktile;
        float* nxt = (kt & 1) ? ktile : vtile;
        if (kt < 7) {   // prefetch next K tile into the other buffer
            const int kloc = t >> 1, dd = (t & 1) * 32;
            const float* src = Tks + ((size_t)(kt+1)*128 + kloc)*64 + dd;
            float* dst = nxt + kloc*68 + dd;
#pragma unroll
            for (int jj = 0; jj < 8; jj++) *(float4*)(dst + jj*4) = *(const float4*)(src + jj*4);
        }
        float4 a0[4], a1[4];
#pragma unroll
        for (int j = 0; j < 4; j++) { a0[j] = make_float4(0,0,0,0); a1[j] = make_float4(0,0,0,0); }
        const float4* q0v = (const float4*)(qv + (2*qp)*68);
        const float4* q1v = (const float4*)(qv + (2*qp+1)*68);
#pragma unroll
        for (int d4 = 0; d4 < 16; d4++) {
            const float4 f0 = q0v[d4], f1 = q1v[d4];
#pragma unroll
            for (int j = 0; j < 4; j++) {
                const float4 kf = *(const float4*)(cur + (kb + 32*j)*68 + d4*4);
                a0[j].x += f0.x*kf.x; a0[j].y += f0.y*kf.y; a0[j].z += f0.z*kf.z; a0[j].w += f0.w*kf.w;
                a1[j].x += f1.x*kf.x; a1[j].y += f1.y*kf.y; a1[j].z += f1.z*kf.z; a1[j].w += f1.w*kf.w;
            }
        }
#pragma unroll
        for (int j = 0; j < 4; j++) {
            const float mv = maskS[kt*128 + 32*j + kb];
            uv0[kt*4+j] = fmap((a0[j].x + a0[j].y + a0[j].z + a0[j].w) * 0.125f + mv);
            uv1[kt*4+j] = fmap((a1[j].x + a1[j].y + a1[j].z + a1[j].w) * 0.125f + mv);
        }
        __syncthreads();
    }

    // dual binary search (exact kth-largest in monotone uint space)
    unsigned lo0 = 0u, hi0 = 0xFFFFFFFFu, lo1 = 0u, hi1 = 0xFFFFFFFFu;
#pragma unroll 1
    for (int it = 0; it < 32; it++) {
        const unsigned d0 = hi0 - lo0, d1 = hi1 - lo1;
        const unsigned mid0 = lo0 + (d0 >> 1) + (d0 & 1u);
        const unsigned mid1 = lo1 + (d1 >> 1) + (d1 & 1u);
        unsigned c0 = 0, c1 = 0;
#pragma unroll
        for (int i = 0; i < 32; i++) {
            c0 += (uv0[i] >= mid0) ? 1u : 0u;
            c1 += (uv1[i] >= mid1) ? 1u : 0u;
        }
        const unsigned packed = wredsumu(c0 | (c1 << 16));
        const unsigned t0 = packed & 0xFFFFu, t1 = packed >> 16;
        if (t0 >= TOPK) lo0 = mid0; else hi0 = mid0 - 1u;
        if (t1 >= TOPK) lo1 = mid1; else hi1 = mid1 - 1u;
    }
    // keep bitmask via ballots
#pragma unroll
    for (int i = 0; i < 32; i++) {
        const unsigned b0 = __ballot_sync(0xffffffffu, uv0[i] >= lo0);
        const unsigned b1 = __ballot_sync(0xffffffffu, uv1[i] >= lo1);
        if (kb == 0) { keepm[(2*qp)*32 + i] = b0; keepm[(2*qp+1)*32 + i] = b1; }
    }
    __syncthreads();

    // ---- Phase B: est branch (dense softmax qa.ka, @ va) ----
    attn_phase<false>(t, Tqa + (size_t)q0*64, Tka, Tva, maskS,
                      qv, ktile, vtile, pbuf, keepm, fac, l_sh, oaccB);
    // ---- Phase C: sparse branch (keep-masked softmax q.k, @ v) ----
    attn_phase<true>(t, Tq + (size_t)q0*64, Tk, Tv, maskS,
                     qv, ktile, vtile, pbuf, keepm, fac, l_sh, oaccC);

    for (int i = t; i < 16*64; i += 256) {
        const int qq = i >> 6, d = i & 63;
        const float val = oaccB[qq*68 + d] + oaccC[qq*68 + d];
        out[((size_t)(b_*1024 + q0 + qq))*1024 + (head & 15)*64 + d] = val;
    }
}

// ---------------- host ----------------
extern "C" void kernel_launch(void* const* d_in, const int* in_sizes, int n_in,
                              void* d_out, int out_size) {
    const float* x  = (const float*)d_in[0];
    const float* am = (const float*)d_in[1];
    const float* Wq = (const float*)d_in[2]; const float* bq = (const float*)d_in[3];
    const float* Wk = (const float*)d_in[4]; const float* bk = (const float*)d_in[5];
    const float* Wv = (const float*)d_in[6]; const float* bv = (const float*)d_in[7];
    const float* A[8]; const float* Bm[8];
    for (int i = 0; i < 8; i++) { A[i] = (const float*)d_in[8 + 2*i]; Bm[i] = (const float*)d_in[9 + 2*i]; }
    float* out = (float*)d_out;

    cudaFuncSetAttribute(k_attention, cudaFuncAttributeMaxDynamicSharedMemorySize, SMEM_BYTES);

    k_base_gemm<<<dim3(8, 16, 3), 256>>>(x, Wq, bq, Wk, bk, Wv, bv);
    k_xa_gemm<<<dim3(32, 8), 256>>>(x, A[0],A[1],A[2],A[3],A[4],A[5],A[6],A[7]);
    k_expand<<<dim3(16, 32, 8), 256>>>(Bm[0],Bm[1],Bm[2],Bm[3],Bm[4],Bm[5],Bm[6],Bm[7]);
    k_attention<<<dim3(64, 32), 256, SMEM_BYTES>>>(am, out);
}

// round 8
// speedup vs baseline: 1.5938x; 1.2123x over previous
#include <cuda_runtime.h>
#include <cstdint>

// B=2, S=1024, H=1024, NH=16, HD=64, R=32, TOPK=128
#define TOPK 128

// device scratch (no allocation allowed)
__device__ __align__(16) float g_t[3u * 2048u * 1024u];         // tq,tk,tv
__device__ __align__(16) float g_xa[2048u * 256u];              // x @ [A0..A7]
__device__ __align__(16) float g_heads[8u * 32u * 1024u * 64u]; // [br][b*16+h][s][d]

// ---------------- Kernel 1: t_z = x @ W_z + b_z (two-level FFMA, R4) --------
__global__ void __launch_bounds__(256) k_base_gemm(
    const float* __restrict__ x,
    const float* __restrict__ W0, const float* __restrict__ b0,
    const float* __restrict__ W1, const float* __restrict__ b1,
    const float* __restrict__ W2, const float* __restrict__ b2)
{
    const int z = blockIdx.z;
    const float* W    = (z == 0) ? W0 : ((z == 1) ? W1 : W2);
    const float* bias = (z == 0) ? b0 : ((z == 1) ? b1 : b2);
    float* C = g_t + (size_t)z * 2048u * 1024u;

    const int m0 = blockIdx.y * 128, n0 = blockIdx.x * 128;
    __shared__ __align__(16) float As[16][128];
    __shared__ __align__(16) float Bs[16][128];

    const int t = threadIdx.x, ty = t >> 4, tx = t & 15;
    float acc[8][8], part[8][8];
#pragma unroll
    for (int i = 0; i < 8; i++)
#pragma unroll
        for (int j = 0; j < 8; j++) acc[i][j] = 0.f;

    const int am = t >> 1, ak = (t & 1) * 8;
    const int bk = t >> 4, bn = (t & 15) * 8;

    for (int kO = 0; kO < 1024; kO += 64) {
#pragma unroll
        for (int i = 0; i < 8; i++)
#pragma unroll
            for (int j = 0; j < 8; j++) part[i][j] = 0.f;

        for (int kt = 0; kt < 4; kt++) {
            const int k0 = kO + kt * 16;
            float4 a0 = *(const float4*)(x + (size_t)(m0 + am) * 1024 + k0 + ak);
            float4 a1 = *(const float4*)(x + (size_t)(m0 + am) * 1024 + k0 + ak + 4);
            float4 w0 = *(const float4*)(W + (size_t)(k0 + bk) * 1024 + n0 + bn);
            float4 w1 = *(const float4*)(W + (size_t)(k0 + bk) * 1024 + n0 + bn + 4);
            As[ak + 0][am] = a0.x; As[ak + 1][am] = a0.y; As[ak + 2][am] = a0.z; As[ak + 3][am] = a0.w;
            As[ak + 4][am] = a1.x; As[ak + 5][am] = a1.y; As[ak + 6][am] = a1.z; As[ak + 7][am] = a1.w;
            *(float4*)&Bs[bk][bn] = w0;  *(float4*)&Bs[bk][bn + 4] = w1;
            __syncthreads();
#pragma unroll
            for (int kk = 0; kk < 16; kk++) {
                float a[8], b[8];
                *(float4*)&a[0] = *(const float4*)&As[kk][ty * 8];
                *(float4*)&a[4] = *(const float4*)&As[kk][ty * 8 + 4];
                *(float4*)&b[0] = *(const float4*)&Bs[kk][tx * 8];
                *(float4*)&b[4] = *(const float4*)&Bs[kk][tx * 8 + 4];
#pragma unroll
                for (int i = 0; i < 8; i++)
#pragma unroll
                    for (int j = 0; j < 8; j++) part[i][j] += a[i] * b[j];
            }
            __syncthreads();
        }
#pragma unroll
        for (int i = 0; i < 8; i++)
#pragma unroll
            for (int j = 0; j < 8; j++) acc[i][j] += part[i][j];
    }
#pragma unroll
    for (int i = 0; i < 8; i++) {
        const int row = m0 + ty * 8 + i;
#pragma unroll
        for (int j4 = 0; j4 < 2; j4++) {
            const int col = n0 + tx * 8 + j4 * 4;
            float4 bb = *(const float4*)(bias + col);
            float4 o;
            o.x = acc[i][j4*4+0] + bb.x; o.y = acc[i][j4*4+1] + bb.y;
            o.z = acc[i][j4*4+2] + bb.z; o.w = acc[i][j4*4+3] + bb.w;
            *(float4*)(C + (size_t)row * 1024 + col) = o;
        }
    }
}

// ---------------- Kernel 2: xa[:, br*32:br*32+32] = x @ A_br ----------------
__global__ void __launch_bounds__(256) k_xa_gemm(
    const float* __restrict__ x,
    const float* A0, const float* A1, const float* A2, const float* A3,
    const float* A4, const float* A5, const float* A6, const float* A7)
{
    const int br = blockIdx.y;
    const float* A;
    switch (br) { case 0: A=A0; break; case 1: A=A1; break; case 2: A=A2; break; case 3: A=A3; break;
                  case 4: A=A4; break; case 5: A=A5; break; case 6: A=A6; break; default: A=A7; }
    const int m0 = blockIdx.x * 64;
    __shared__ float xs[32][64];
    __shared__ __align__(16) float as_[32][32];

    const int t = threadIdx.x;
    const int mm = t >> 2, rb = (t & 3) * 8;
    const int lm = t >> 2, lk = (t & 3) * 8;
    const int akk = t >> 3, ar = (t & 7) * 4;

    float acc[8];
#pragma unroll
    for (int j = 0; j < 8; j++) acc[j] = 0.f;

    for (int k0 = 0; k0 < 1024; k0 += 32) {
        float4 x0 = *(const float4*)(x + (size_t)(m0 + lm) * 1024 + k0 + lk);
        float4 x1 = *(const float4*)(x + (size_t)(m0 + lm) * 1024 + k0 + lk + 4);
        float4 a4 = *(const float4*)(A + (size_t)(k0 + akk) * 32 + ar);
        xs[lk+0][lm]=x0.x; xs[lk+1][lm]=x0.y; xs[lk+2][lm]=x0.z; xs[lk+3][lm]=x0.w;
        xs[lk+4][lm]=x1.x; xs[lk+5][lm]=x1.y; xs[lk+6][lm]=x1.z; xs[lk+7][lm]=x1.w;
        *(float4*)&as_[akk][ar] = a4;
        __syncthreads();
        float part[8];
#pragma unroll
        for (int j = 0; j < 8; j++) part[j] = 0.f;
#pragma unroll
        for (int kk = 0; kk < 32; kk++) {
            const float xv = xs[kk][mm];
#pragma unroll
            for (int j = 0; j < 8; j++) part[j] += xv * as_[kk][rb + j];
        }
#pragma unroll
        for (int j = 0; j < 8; j++) acc[j] += part[j];
        __syncthreads();
    }
    *(float4*)(g_xa + (size_t)(m0+mm)*256 + br*32 + rb)   = make_float4(acc[0],acc[1],acc[2],acc[3]);
    *(float4*)(g_xa + (size_t)(m0+mm)*256 + br*32 + rb+4) = make_float4(acc[4],acc[5],acc[6],acc[7]);
}

// ------- Kernel 3: heads[br] = base(br) + xa_br @ B_br, head layout -------
__global__ void __launch_bounds__(256) k_expand(
    const float* B0, const float* B1, const float* B2, const float* B3,
    const float* B4, const float* B5, const float* B6, const float* B7)
{
    const int br = blockIdx.z;
    const float* Bm;
    switch (br) { case 0: Bm=B0; break; case 1: Bm=B1; break; case 2: Bm=B2; break; case 3: Bm=B3; break;
                  case 4: Bm=B4; break; case 5: Bm=B5; break; case 6: Bm=B6; break; default: Bm=B7; }
    const int baseIdx = (br == 2 || br == 7) ? 2 : ((br == 1 || br == 4 || br == 6) ? 1 : 0);
    const float* tb = g_t + (size_t)baseIdx * 2048u * 1024u;

    const int m0 = blockIdx.y * 64, n0 = blockIdx.x * 64;
    __shared__ __align__(16) float xaS[32][68];
    __shared__ __align__(16) float bS[32][68];

    const int t = threadIdx.x;
    {
        const int m = t >> 2, rr = (t & 3) * 8;
        float4 v0 = *(const float4*)(g_xa + (size_t)(m0+m)*256 + br*32 + rr);
        float4 v1 = *(const float4*)(g_xa + (size_t)(m0+m)*256 + br*32 + rr + 4);
        xaS[rr+0][m]=v0.x; xaS[rr+1][m]=v0.y; xaS[rr+2][m]=v0.z; xaS[rr+3][m]=v0.w;
        xaS[rr+4][m]=v1.x; xaS[rr+5][m]=v1.y; xaS[rr+6][m]=v1.z; xaS[rr+7][m]=v1.w;
    }
    {
        const int r = t >> 3, nn = (t & 7) * 8;
        *(float4*)&bS[r][nn]   = *(const float4*)(Bm + (size_t)r*1024 + n0 + nn);
        *(float4*)&bS[r][nn+4] = *(const float4*)(Bm + (size_t)r*1024 + n0 + nn + 4);
    }
    __syncthreads();

    const int ty = t >> 4, tx = t & 15;
    float acc[4][4];
#pragma unroll
    for (int i = 0; i < 4; i++)
#pragma unroll
        for (int j = 0; j < 4; j++) acc[i][j] = 0.f;
#pragma unroll
    for (int r = 0; r < 32; r++) {
        float4 a4 = *(const float4*)&xaS[r][ty*4];
        float4 b4 = *(const float4*)&bS[r][tx*4];
        acc[0][0]+=a4.x*b4.x; acc[0][1]+=a4.x*b4.y; acc[0][2]+=a4.x*b4.z; acc[0][3]+=a4.x*b4.w;
        acc[1][0]+=a4.y*b4.x; acc[1][1]+=a4.y*b4.y; acc[1][2]+=a4.y*b4.z; acc[1][3]+=a4.y*b4.w;
        acc[2][0]+=a4.z*b4.x; acc[2][1]+=a4.z*b4.y; acc[2][2]+=a4.z*b4.z; acc[2][3]+=a4.z*b4.w;
        acc[3][0]+=a4.w*b4.x; acc[3][1]+=a4.w*b4.y; acc[3][2]+=a4.w*b4.z; acc[3][3]+=a4.w*b4.w;
    }

    const int h = blockIdx.x;
#pragma unroll
    for (int i = 0; i < 4; i++) {
        const int m = m0 + ty*4 + i, b_ = m >> 10, s = m & 1023;
        float4 base = *(const float4*)(tb + (size_t)m*1024 + n0 + tx*4);
        float4 o;
        o.x=acc[i][0]+base.x; o.y=acc[i][1]+base.y; o.z=acc[i][2]+base.z; o.w=acc[i][3]+base.w;
        *(float4*)(g_heads + (((size_t)br*32 + b_*16 + h)*1024 + s)*64 + tx*4) = o;
    }
}

// ---------------- Kernel 4: attention v3 (64q CTA, 512 threads) ------------
__device__ __forceinline__ unsigned fmap(float f) {
    unsigned u = __float_as_uint(f);
    return (u & 0x80000000u) ? ~u : (u | 0x80000000u);
}
__device__ __forceinline__ float wredmax(float v) {
#pragma unroll
    for (int o = 16; o > 0; o >>= 1) v = fmaxf(v, __shfl_xor_sync(0xffffffffu, v, o));
    return v;
}
__device__ __forceinline__ float wredsum(float v) {
#pragma unroll
    for (int o = 16; o > 0; o >>= 1) v += __shfl_xor_sync(0xffffffffu, v, o);
    return v;
}
__device__ __forceinline__ unsigned wredsumu(unsigned v) {
#pragma unroll
    for (int o = 16; o > 0; o >>= 1) v += __shfl_xor_sync(0xffffffffu, v, o);
    return v;
}

// smem float offsets
#define OFF_KT   0
#define OFF_VT   8704              // 128*68
#define OFF_QV   (2*8704)          // 64*68
#define OFF_MASK (OFF_QV + 64*68)
#define OFF_PBUF (OFF_MASK + 1024) // 64*128
#define OFF_OB   (OFF_PBUF + 64*128)
#define OFF_OC   (OFF_OB + 64*68)
#define OFF_FAC  (OFF_OC + 64*68)
#define OFF_LSH  (OFF_FAC + 64)
#define OFF_KEEP (OFF_LSH + 64)    // 64*32 unsigned
#define SMEM_FLOATS (OFF_KEEP + 64*32)
#define SMEM_BYTES  (SMEM_FLOATS * 4)   // 167,424 B

template<bool KEEP>
__device__ void attn_phase(
    const int t,
    const float* __restrict__ qptr, const float* __restrict__ kptr,
    const float* __restrict__ vptr, const float* __restrict__ maskS,
    float* qv, float* ktile, float* vtile, float* pbuf,
    const unsigned* __restrict__ keepm, float* fac, float* l_sh, float* oacc)
{
    {   // load 64 query rows
        const int q = t >> 3, d = (t & 7) * 8;
        *(float4*)&qv[q*68 + d]     = *(const float4*)(qptr + (size_t)q*64 + d);
        *(float4*)&qv[q*68 + d + 4] = *(const float4*)(qptr + (size_t)q*64 + d + 4);
    }
    for (int i = t; i < 64*68; i += 512) oacc[i] = 0.f;

    float o[8][4];
#pragma unroll
    for (int i = 0; i < 8; i++)
#pragma unroll
        for (int j = 0; j < 4; j++) o[i][j] = 0.f;

    const int w  = t >> 5;                  // warp 0..15 -> queries 4w..4w+3
    const int kb = t & 31;                  // key slot
    const int dg = t & 15, kg = (t >> 4) & 3, qg = t >> 6;   // pv: queries 8qg..8qg+7
    float m_[4], l_[4];
#pragma unroll
    for (int qi = 0; qi < 4; qi++) { m_[qi] = -1e30f; l_[qi] = 0.f; }
    __syncthreads();

    for (int kt = 0; kt < 8; kt++) {
        {   // load K and V tiles: 512 threads, row t>>2, 16-float segment
            const int kloc = t >> 2, dd = (t & 3) * 16;
            const float* ksrc = kptr + ((size_t)kt*128 + kloc)*64 + dd;
            const float* vsrc = vptr + ((size_t)kt*128 + kloc)*64 + dd;
            float4 kr[4], vr[4];
#pragma unroll
            for (int jj = 0; jj < 4; jj++) kr[jj] = *(const float4*)(ksrc + jj*4);
#pragma unroll
            for (int jj = 0; jj < 4; jj++) vr[jj] = *(const float4*)(vsrc + jj*4);
            float* kdst = ktile + kloc*68 + dd;
            float* vdst = vtile + kloc*68 + dd;
#pragma unroll
            for (int jj = 0; jj < 4; jj++) *(float4*)(kdst + jj*4) = kr[jj];
#pragma unroll
            for (int jj = 0; jj < 4; jj++) *(float4*)(vdst + jj*4) = vr[jj];
        }
        __syncthreads();                    // S1

        // scores: 4 queries x 4 keys per thread (scalar accumulators)
        float s[4][4];
#pragma unroll
        for (int qi = 0; qi < 4; qi++)
#pragma unroll
            for (int j = 0; j < 4; j++) s[qi][j] = 0.f;
#pragma unroll
        for (int d4 = 0; d4 < 16; d4++) {
            float4 qf[4];
#pragma unroll
            for (int qi = 0; qi < 4; qi++)
                qf[qi] = *(const float4*)(qv + (4*w + qi)*68 + d4*4);
#pragma unroll
            for (int j = 0; j < 4; j++) {
                const float4 kf = *(const float4*)(ktile + (kb + 32*j)*68 + d4*4);
#pragma unroll
                for (int qi = 0; qi < 4; qi++)
                    s[qi][j] += qf[qi].x*kf.x + qf[qi].y*kf.y + qf[qi].z*kf.z + qf[qi].w*kf.w;
            }
        }
#pragma unroll
        for (int qi = 0; qi < 4; qi++) {
            bool kp[4];
            float tmx = -1e30f;
#pragma unroll
            for (int j = 0; j < 4; j++) {
                const int key = kt*128 + 32*j + kb;
                float sv = s[qi][j] * 0.125f + maskS[key];
                if (KEEP) {
                    kp[j] = (keepm[(4*w + qi)*32 + kt*4 + j] >> kb) & 1u;
                    if (!kp[j]) sv = -1e30f;
                } else kp[j] = true;
                s[qi][j] = sv;
                tmx = fmaxf(tmx, sv);
            }
            tmx = wredmax(tmx);
            const float nm = fmaxf(m_[qi], tmx);
            const float fr = __expf(m_[qi] - nm);
            m_[qi] = nm;
            if (kb == 0) fac[4*w + qi] = fr;
            float ps = 0.f;
#pragma unroll
            for (int j = 0; j < 4; j++) {
                float p = __expf(s[qi][j] - nm);
                if (KEEP && !kp[j]) p = 0.f;
                pbuf[(4*w + qi)*128 + 32*j + kb] = p;
                ps += p;
            }
            ps = wredsum(ps);
            l_[qi] = l_[qi] * fr + ps;
        }
        __syncthreads();                    // S2: fac + pbuf visible

        // pv: 8 queries per thread
        {
            float fq[8];
#pragma unroll
            for (int qi = 0; qi < 8; qi++) fq[qi] = fac[8*qg + qi];
#pragma unroll
            for (int qi = 0; qi < 8; qi++) {
                o[qi][0]*=fq[qi]; o[qi][1]*=fq[qi]; o[qi][2]*=fq[qi]; o[qi][3]*=fq[qi];
            }
#pragma unroll
            for (int kk4 = 0; kk4 < 8; kk4++) {
                const int base2 = kg*32 + kk4*4;
                const float4 v0 = *(const float4*)(vtile + (base2+0)*68 + dg*4);
                const float4 v1 = *(const float4*)(vtile + (base2+1)*68 + dg*4);
                const float4 v2 = *(const float4*)(vtile + (base2+2)*68 + dg*4);
                const float4 v3 = *(const float4*)(vtile + (base2+3)*68 + dg*4);
#pragma unroll
                for (int qi = 0; qi < 8; qi++) {
                    const float4 p4 = *(const float4*)(pbuf + (8*qg + qi)*128 + base2);
                    o[qi][0] += p4.x*v0.x + p4.y*v1.x + p4.z*v2.x + p4.w*v3.x;
                    o[qi][1] += p4.x*v0.y + p4.y*v1.y + p4.z*v2.y + p4.w*v3.y;
                    o[qi][2] += p4.x*v0.z + p4.y*v1.z + p4.z*v2.z + p4.w*v3.z;
                    o[qi][3] += p4.x*v0.w + p4.y*v1.w + p4.z*v2.w + p4.w*v3.w;
                }
            }
        }
        __syncthreads();                    // S3
    }

    if (kb == 0) {
#pragma unroll
        for (int qi = 0; qi < 4; qi++) l_sh[4*w + qi] = l_[qi];
    }
    for (int turn = 0; turn < 4; turn++) {
        if (kg == turn) {
#pragma unroll
            for (int qi = 0; qi < 8; qi++) {
                float* dst = oacc + (8*qg + qi)*68 + dg*4;
                dst[0]+=o[qi][0]; dst[1]+=o[qi][1]; dst[2]+=o[qi][2]; dst[3]+=o[qi][3];
            }
        }
        __syncthreads();
    }
    for (int i = t; i < 64*64; i += 512) {
        const int qq = i >> 6, d = i & 63;
        oacc[qq*68 + d] *= 0.5f / l_sh[qq];
    }
    __syncthreads();
}

__global__ void __launch_bounds__(512) k_attention(
    const float* __restrict__ am, float* __restrict__ out)
{
    extern __shared__ float smf[];
    float* ktile = smf + OFF_KT;
    float* vtile = smf + OFF_VT;
    float* qv    = smf + OFF_QV;
    float* maskS = smf + OFF_MASK;
    float* pbuf  = smf + OFF_PBUF;
    float* oaccB = smf + OFF_OB;
    float* oaccC = smf + OFF_OC;
    float* fac   = smf + OFF_FAC;
    float* l_sh  = smf + OFF_LSH;
    unsigned* keepm = (unsigned*)(smf + OFF_KEEP);

    const int t = threadIdx.x;
    const int head = blockIdx.y;        // b*16 + h
    const int q0 = blockIdx.x * 64;
    const int b_ = head >> 4;

    for (int i = t; i < 1024; i += 512) maskS[i] = am[b_*1024 + i];

    const size_t hs = (size_t)1024 * 64;
    const float* Tq  = g_heads + (0u*32 + head)*hs;
    const float* Tk  = g_heads + (1u*32 + head)*hs;
    const float* Tv  = g_heads + (2u*32 + head)*hs;
    const float* Tqs = g_heads + (3u*32 + head)*hs;
    const float* Tks = g_heads + (4u*32 + head)*hs;
    const float* Tqa = g_heads + (5u*32 + head)*hs;
    const float* Tka = g_heads + (6u*32 + head)*hs;
    const float* Tva = g_heads + (7u*32 + head)*hs;

    // ---- Phase A: qs.ks scores in registers, exact kth, keep bitmask ----
    {   // load 64 qs rows
        const int q = t >> 3, d = (t & 7) * 8;
        *(float4*)&qv[q*68 + d]     = *(const float4*)(Tqs + (size_t)(q0 + q)*64 + d);
        *(float4*)&qv[q*68 + d + 4] = *(const float4*)(Tqs + (size_t)(q0 + q)*64 + d + 4);
    }
    __syncthreads();

    const int qp = t >> 5, kb = t & 31;
#pragma unroll 1
    for (int pass = 0; pass < 2; pass++) {
        const int qA = pass*32 + 2*qp, qB = qA + 1;
        unsigned uv0[32], uv1[32];

        {   // prologue: tile 0 -> ktile
            const int kloc = t >> 2, dd = (t & 3) * 16;
            const float* src = Tks + (size_t)kloc*64 + dd;
            float* dst = ktile + kloc*68 + dd;
#pragma unroll
            for (int jj = 0; jj < 4; jj++) *(float4*)(dst + jj*4) = *(const float4*)(src + jj*4);
        }
        __syncthreads();

#pragma unroll 1
        for (int kt = 0; kt < 8; kt++) {
            float* cur = (kt & 1) ? vtile : ktile;
            float* nxt = (kt & 1) ? ktile : vtile;
            if (kt < 7) {   // prefetch next tile
                const int kloc = t >> 2, dd = (t & 3) * 16;
                const float* src = Tks + ((size_t)(kt+1)*128 + kloc)*64 + dd;
                float* dst = nxt + kloc*68 + dd;
#pragma unroll
                for (int jj = 0; jj < 4; jj++) *(float4*)(dst + jj*4) = *(const float4*)(src + jj*4);
            }
            float s0[4] = {0.f,0.f,0.f,0.f}, s1[4] = {0.f,0.f,0.f,0.f};
            const float4* q0v = (const float4*)(qv + qA*68);
            const float4* q1v = (const float4*)(qv + qB*68);
#pragma unroll
            for (int d4 = 0; d4 < 16; d4++) {
                const float4 f0 = q0v[d4], f1 = q1v[d4];
#pragma unroll
                for (int j = 0; j < 4; j++) {
                    const float4 kf = *(const float4*)(cur + (kb + 32*j)*68 + d4*4);
                    s0[j] += f0.x*kf.x + f0.y*kf.y + f0.z*kf.z + f0.w*kf.w;
                    s1[j] += f1.x*kf.x + f1.y*kf.y + f1.z*kf.z + f1.w*kf.w;
                }
            }
#pragma unroll
            for (int j = 0; j < 4; j++) {
                const float mv = maskS[kt*128 + 32*j + kb];
                uv0[kt*4+j] = fmap(s0[j] * 0.125f + mv);
                uv1[kt*4+j] = fmap(s1[j] * 0.125f + mv);
            }
            __syncthreads();
        }

        // dual exact kth-largest binary search in monotone uint space
        unsigned lo0 = 0u, hi0 = 0xFFFFFFFFu, lo1 = 0u, hi1 = 0xFFFFFFFFu;
#pragma unroll 1
        for (int it = 0; it < 32; it++) {
            const unsigned d0 = hi0 - lo0, d1 = hi1 - lo1;
            const unsigned mid0 = lo0 + (d0 >> 1) + (d0 & 1u);
            const unsigned mid1 = lo1 + (d1 >> 1) + (d1 & 1u);
            unsigned c0 = 0, c1 = 0;
#pragma unroll
            for (int i = 0; i < 32; i++) {
                c0 += (uv0[i] >= mid0) ? 1u : 0u;
                c1 += (uv1[i] >= mid1) ? 1u : 0u;
            }
            const unsigned packed = wredsumu(c0 | (c1 << 16));
            const unsigned t0 = packed & 0xFFFFu, t1 = packed >> 16;
            if (t0 >= TOPK) lo0 = mid0; else hi0 = mid0 - 1u;
            if (t1 >= TOPK) lo1 = mid1; else hi1 = mid1 - 1u;
        }
#pragma unroll
        for (int i = 0; i < 32; i++) {
            const unsigned b0 = __ballot_sync(0xffffffffu, uv0[i] >= lo0);
            const unsigned b1 = __ballot_sync(0xffffffffu, uv1[i] >= lo1);
            if (kb == 0) { keepm[qA*32 + i] = b0; keepm[qB*32 + i] = b1; }
        }
        __syncthreads();
    }

    // ---- Phase B: est branch (dense softmax qa.ka, @ va) ----
    attn_phase<false>(t, Tqa + (size_t)q0*64, Tka, Tva, maskS,
                      qv, ktile, vtile, pbuf, keepm, fac, l_sh, oaccB);
    // ---- Phase C: sparse branch (keep-masked softmax q.k, @ v) ----
    attn_phase<true>(t, Tq + (size_t)q0*64, Tk, Tv, maskS,
                     qv, ktile, vtile, pbuf, keepm, fac, l_sh, oaccC);

    for (int i = t; i < 64*64; i += 512) {
        const int qq = i >> 6, d = i & 63;
        const float val = oaccB[qq*68 + d] + oaccC[qq*68 + d];
        out[((size_t)(b_*1024 + q0 + qq))*1024 + (head & 15)*64 + d] = val;
    }
}

// ---------------- host ----------------
extern "C" void kernel_launch(void* const* d_in, const int* in_sizes, int n_in,
                              void* d_out, int out_size) {
    const float* x  = (const float*)d_in[0];
    const float* am = (const float*)d_in[1];
    const float* Wq = (const float*)d_in[2]; const float* bq = (const float*)d_in[3];
    const float* Wk = (const float*)d_in[4]; const float* bk = (const float*)d_in[5];
    const float* Wv = (const float*)d_in[6]; const float* bv = (const float*)d_in[7];
    const float* A[8]; const float* Bm[8];
    for (int i = 0; i < 8; i++) { A[i] = (const float*)d_in[8 + 2*i]; Bm[i] = (const float*)d_in[9 + 2*i]; }
    float* out = (float*)d_out;

    cudaFuncSetAttribute(k_attention, cudaFuncAttributeMaxDynamicSharedMemorySize, SMEM_BYTES);

    k_base_gemm<<<dim3(8, 16, 3), 256>>>(x, Wq, bq, Wk, bk, Wv, bv);
    k_xa_gemm<<<dim3(32, 8), 256>>>(x, A[0],A[1],A[2],A[3],A[4],A[5],A[6],A[7]);
    k_expand<<<dim3(16, 32, 8), 256>>>(Bm[0],Bm[1],Bm[2],Bm[3],Bm[4],Bm[5],Bm[6],Bm[7]);
    k_attention<<<dim3(16, 32), 512, SMEM_BYTES>>>(am, out);
}